// round 1
// baseline (speedup 1.0000x reference)
#include <cuda_runtime.h>
#include <math.h>

#define BB 2
#define SS 2048
#define DD 1024
#define HH 16
#define DHD 64
#define NROWS (BB*SS)          /* 4096 */
#define ATTN_SCALE 0.125f      /* 1/sqrt(64) */

/* log2(10000)/32 */
#define ROPE_LOG2C 0.4152410118609203f

/* Scratch (allocation-free rule: __device__ globals). 4 x 16MB = 64MB */
__device__ float g_q[BB*HH*SS*DHD];
__device__ float g_k[BB*HH*SS*DHD];
__device__ float g_v[BB*HH*SS*DHD];
__device__ float g_ctx[(size_t)NROWS*DD];

/* ------------------------------------------------------------------ */
/* QKV projection GEMM: X[4096,1024] @ W[1024,1024] with RoPE epilogue */
/* 128x128 tile, BK=16, 256 threads, 8x8 per thread                   */
/* ------------------------------------------------------------------ */
__global__ __launch_bounds__(256, 2)
void qkv_kernel(const float* __restrict__ X,
                const float* __restrict__ Wq,
                const float* __restrict__ Wk,
                const float* __restrict__ Wv)
{
    const int which = blockIdx.z;
    const float* __restrict__ W = (which == 0) ? Wq : ((which == 1) ? Wk : Wv);
    float* __restrict__ dst = (which == 0) ? g_q : ((which == 1) ? g_k : g_v);

    __shared__ __align__(16) float As[16][132];   /* transposed A tile [k][m] */
    __shared__ __align__(16) float Bs[16][132];   /* B tile [k][n] */

    const int tid = threadIdx.x;
    const int tx = tid & 15, ty = tid >> 4;
    const int row0 = blockIdx.y * 128;
    const int col0 = blockIdx.x * 128;

    float acc[8][8];
#pragma unroll
    for (int i = 0; i < 8; i++)
#pragma unroll
        for (int j = 0; j < 8; j++) acc[i][j] = 0.f;

    for (int kt = 0; kt < DD; kt += 16) {
        /* load A 128x16 (transpose into As[k][m]) */
#pragma unroll
        for (int w = 0; w < 2; w++) {
            int fi = tid + 256 * w;
            int r = fi >> 2, q = fi & 3;
            float4 v = *reinterpret_cast<const float4*>(
                &X[(size_t)(row0 + r) * DD + kt + q * 4]);
            As[q * 4 + 0][r] = v.x;
            As[q * 4 + 1][r] = v.y;
            As[q * 4 + 2][r] = v.z;
            As[q * 4 + 3][r] = v.w;
        }
        /* load B 16x128 */
#pragma unroll
        for (int w = 0; w < 2; w++) {
            int fi = tid + 256 * w;
            int r = fi >> 5, q = fi & 31;
            float4 v = *reinterpret_cast<const float4*>(
                &W[(size_t)(kt + r) * DD + col0 + q * 4]);
            *reinterpret_cast<float4*>(&Bs[r][q * 4]) = v;
        }
        __syncthreads();

#pragma unroll
        for (int k = 0; k < 16; k++) {
            float a[8], b[8];
            float4 t;
            t = *reinterpret_cast<const float4*>(&As[k][ty * 8]);
            a[0] = t.x; a[1] = t.y; a[2] = t.z; a[3] = t.w;
            t = *reinterpret_cast<const float4*>(&As[k][ty * 8 + 4]);
            a[4] = t.x; a[5] = t.y; a[6] = t.z; a[7] = t.w;
            t = *reinterpret_cast<const float4*>(&Bs[k][tx * 8]);
            b[0] = t.x; b[1] = t.y; b[2] = t.z; b[3] = t.w;
            t = *reinterpret_cast<const float4*>(&Bs[k][tx * 8 + 4]);
            b[4] = t.x; b[5] = t.y; b[6] = t.z; b[7] = t.w;
#pragma unroll
            for (int i = 0; i < 8; i++)
#pragma unroll
                for (int j = 0; j < 8; j++)
                    acc[i][j] = fmaf(a[i], b[j], acc[i][j]);
        }
        __syncthreads();
    }

    /* epilogue: write as [B, H, S, Dh]; RoPE (interleaved) for Q and K */
    const int col = col0 + tx * 8;       /* 8 cols stay inside one head */
    const int h  = col >> 6;
    const int dh = col & 63;             /* multiple of 8 -> even */

    if (which < 2) {
#pragma unroll
        for (int i = 0; i < 8; i++) {
            int row = row0 + ty * 8 + i;
            int b_ = row >> 11, s = row & (SS - 1);
            float* drow = dst + ((size_t)(b_ * HH + h) * SS + s) * DHD + dh;
            float sf = (float)s;
#pragma unroll
            for (int jp = 0; jp < 4; jp++) {
                int ip = (dh >> 1) + jp;
                float ang = sf * exp2f(-(float)ip * ROPE_LOG2C);
                float sn, cs;
                sincosf(ang, &sn, &cs);
                float e = acc[i][jp * 2], o = acc[i][jp * 2 + 1];
                drow[jp * 2]     = e * cs - o * sn;
                drow[jp * 2 + 1] = e * sn + o * cs;
            }
        }
    } else {
#pragma unroll
        for (int i = 0; i < 8; i++) {
            int row = row0 + ty * 8 + i;
            int b_ = row >> 11, s = row & (SS - 1);
            float* drow = dst + ((size_t)(b_ * HH + h) * SS + s) * DHD + dh;
#pragma unroll
            for (int j = 0; j < 8; j++) drow[j] = acc[i][j];
        }
    }
}

/* ------------------------------------------------------------------ */
/* Flash attention, fp32, causal. 64x64 tiles, 8 warps.               */
/* Each warp owns 8 q-rows; each lane owns k-cols {lane, lane+32} and */
/* v-dims {lane, lane+32}. ctx written in [B*S, D] layout.            */
/* ------------------------------------------------------------------ */
#define ATTN_SMEM_FLOATS (3 * 64 * 68 + 64 * 64)
#define ATTN_SMEM_BYTES  (ATTN_SMEM_FLOATS * 4)

__global__ __launch_bounds__(256)
void attn_kernel()
{
    extern __shared__ __align__(16) float sm[];
    float (*Qs)[68] = reinterpret_cast<float(*)[68]>(sm);
    float (*Ks)[68] = reinterpret_cast<float(*)[68]>(sm + 64 * 68);
    float (*Vs)[68] = reinterpret_cast<float(*)[68]>(sm + 2 * 64 * 68);
    float (*Ps)[64] = reinterpret_cast<float(*)[64]>(sm + 3 * 64 * 68);

    const int bh = blockIdx.y;
    /* reverse so heaviest causal tiles launch first (load balance) */
    const int qt = gridDim.x - 1 - blockIdx.x;

    const float* __restrict__ Q = g_q + (size_t)bh * SS * DHD;
    const float* __restrict__ K = g_k + (size_t)bh * SS * DHD;
    const float* __restrict__ V = g_v + (size_t)bh * SS * DHD;

    const int tid  = threadIdx.x;
    const int warp = tid >> 5, lane = tid & 31;

    /* load Q tile once */
    for (int i4 = tid; i4 < 64 * 16; i4 += 256) {
        int r = i4 >> 4, q = i4 & 15;
        *reinterpret_cast<float4*>(&Qs[r][q * 4]) =
            *reinterpret_cast<const float4*>(&Q[(size_t)(qt * 64 + r) * DHD + q * 4]);
    }

    float m[8], l[8], o0[8], o1[8];
#pragma unroll
    for (int rr = 0; rr < 8; rr++) { m[rr] = -1e30f; l[rr] = 0.f; o0[rr] = 0.f; o1[rr] = 0.f; }

    for (int kt = 0; kt <= qt; kt++) {
        __syncthreads();   /* prev tile fully consumed (K/V and Ps) */
        for (int i4 = tid; i4 < 64 * 16; i4 += 256) {
            int r = i4 >> 4, q = i4 & 15;
            *reinterpret_cast<float4*>(&Ks[r][q * 4]) =
                *reinterpret_cast<const float4*>(&K[(size_t)(kt * 64 + r) * DHD + q * 4]);
            *reinterpret_cast<float4*>(&Vs[r][q * 4]) =
                *reinterpret_cast<const float4*>(&V[(size_t)(kt * 64 + r) * DHD + q * 4]);
        }
        __syncthreads();

        /* ---- scores: s[rr][c], c in {lane, lane+32} ---- */
        float s0[8], s1[8];
#pragma unroll
        for (int rr = 0; rr < 8; rr++) { s0[rr] = 0.f; s1[rr] = 0.f; }

#pragma unroll
        for (int d4 = 0; d4 < 16; d4++) {
            float4 k0 = *reinterpret_cast<const float4*>(&Ks[lane][d4 * 4]);
            float4 k1 = *reinterpret_cast<const float4*>(&Ks[lane + 32][d4 * 4]);
#pragma unroll
            for (int rr = 0; rr < 8; rr++) {
                float4 q4 = *reinterpret_cast<const float4*>(&Qs[warp * 8 + rr][d4 * 4]);
                s0[rr] = fmaf(q4.x, k0.x, fmaf(q4.y, k0.y, fmaf(q4.z, k0.z, fmaf(q4.w, k0.w, s0[rr]))));
                s1[rr] = fmaf(q4.x, k1.x, fmaf(q4.y, k1.y, fmaf(q4.z, k1.z, fmaf(q4.w, k1.w, s1[rr]))));
            }
        }

        /* ---- online softmax ---- */
        const bool diag = (kt == qt);
#pragma unroll
        for (int rr = 0; rr < 8; rr++) {
            float v0 = s0[rr] * ATTN_SCALE;
            float v1 = s1[rr] * ATTN_SCALE;
            int qrow = warp * 8 + rr;   /* local */
            if (diag) {
                if (lane > qrow)      v0 = -1e30f;
                if (lane + 32 > qrow) v1 = -1e30f;
            }
            float mx = fmaxf(v0, v1);
#pragma unroll
            for (int off = 16; off; off >>= 1)
                mx = fmaxf(mx, __shfl_xor_sync(0xffffffffu, mx, off));
            float mnew = fmaxf(m[rr], mx);
            float p0 = __expf(v0 - mnew);
            float p1 = __expf(v1 - mnew);
            float corr = __expf(m[rr] - mnew);
            float ps = p0 + p1;
#pragma unroll
            for (int off = 16; off; off >>= 1)
                ps += __shfl_xor_sync(0xffffffffu, ps, off);
            l[rr] = l[rr] * corr + ps;
            o0[rr] *= corr;
            o1[rr] *= corr;
            m[rr] = mnew;
            Ps[warp * 8 + rr][lane]      = p0;
            Ps[warp * 8 + rr][lane + 32] = p1;
        }
        __syncwarp();

        /* ---- AV: o[rr][dv], dv in {lane, lane+32} ---- */
#pragma unroll
        for (int c4 = 0; c4 < 16; c4++) {
            float va[4], vb[4];
#pragma unroll
            for (int u = 0; u < 4; u++) {
                va[u] = Vs[c4 * 4 + u][lane];
                vb[u] = Vs[c4 * 4 + u][lane + 32];
            }
#pragma unroll
            for (int rr = 0; rr < 8; rr++) {
                float4 p = *reinterpret_cast<const float4*>(&Ps[warp * 8 + rr][c4 * 4]);
                o0[rr] = fmaf(p.x, va[0], fmaf(p.y, va[1], fmaf(p.z, va[2], fmaf(p.w, va[3], o0[rr]))));
                o1[rr] = fmaf(p.x, vb[0], fmaf(p.y, vb[1], fmaf(p.z, vb[2], fmaf(p.w, vb[3], o1[rr]))));
            }
        }
    }

    /* write ctx in [B*S, D] layout for the output projection */
    const int b_ = bh >> 4, h = bh & 15;
#pragma unroll
    for (int rr = 0; rr < 8; rr++) {
        int srow = qt * 64 + warp * 8 + rr;
        float inv = 1.0f / l[rr];
        float* orow = g_ctx + ((size_t)(b_ * SS + srow)) * DD + h * DHD;
        orow[lane]      = o0[rr] * inv;
        orow[lane + 32] = o1[rr] * inv;
    }
}

/* ------------------------------------------------------------------ */
/* Output projection: ctx[4096,1024] @ Wo + bo -> out                 */
/* ------------------------------------------------------------------ */
__global__ __launch_bounds__(256, 2)
void out_kernel(const float* __restrict__ Wo,
                const float* __restrict__ bo,
                float* __restrict__ out)
{
    __shared__ __align__(16) float As[16][132];
    __shared__ __align__(16) float Bs[16][132];

    const int tid = threadIdx.x;
    const int tx = tid & 15, ty = tid >> 4;
    const int row0 = blockIdx.y * 128;
    const int col0 = blockIdx.x * 128;

    float acc[8][8];
#pragma unroll
    for (int i = 0; i < 8; i++)
#pragma unroll
        for (int j = 0; j < 8; j++) acc[i][j] = 0.f;

    for (int kt = 0; kt < DD; kt += 16) {
#pragma unroll
        for (int w = 0; w < 2; w++) {
            int fi = tid + 256 * w;
            int r = fi >> 2, q = fi & 3;
            float4 v = *reinterpret_cast<const float4*>(
                &g_ctx[(size_t)(row0 + r) * DD + kt + q * 4]);
            As[q * 4 + 0][r] = v.x;
            As[q * 4 + 1][r] = v.y;
            As[q * 4 + 2][r] = v.z;
            As[q * 4 + 3][r] = v.w;
        }
#pragma unroll
        for (int w = 0; w < 2; w++) {
            int fi = tid + 256 * w;
            int r = fi >> 5, q = fi & 31;
            float4 v = *reinterpret_cast<const float4*>(
                &Wo[(size_t)(kt + r) * DD + col0 + q * 4]);
            *reinterpret_cast<float4*>(&Bs[r][q * 4]) = v;
        }
        __syncthreads();

#pragma unroll
        for (int k = 0; k < 16; k++) {
            float a[8], b[8];
            float4 t;
            t = *reinterpret_cast<const float4*>(&As[k][ty * 8]);
            a[0] = t.x; a[1] = t.y; a[2] = t.z; a[3] = t.w;
            t = *reinterpret_cast<const float4*>(&As[k][ty * 8 + 4]);
            a[4] = t.x; a[5] = t.y; a[6] = t.z; a[7] = t.w;
            t = *reinterpret_cast<const float4*>(&Bs[k][tx * 8]);
            b[0] = t.x; b[1] = t.y; b[2] = t.z; b[3] = t.w;
            t = *reinterpret_cast<const float4*>(&Bs[k][tx * 8 + 4]);
            b[4] = t.x; b[5] = t.y; b[6] = t.z; b[7] = t.w;
#pragma unroll
            for (int i = 0; i < 8; i++)
#pragma unroll
                for (int j = 0; j < 8; j++)
                    acc[i][j] = fmaf(a[i], b[j], acc[i][j]);
        }
        __syncthreads();
    }

#pragma unroll
    for (int i = 0; i < 8; i++) {
        int row = row0 + ty * 8 + i;
        float* orow = out + (size_t)row * DD + col0 + tx * 8;
#pragma unroll
        for (int j = 0; j < 8; j++)
            orow[j] = acc[i][j] + bo[col0 + tx * 8 + j];
    }
}

/* ------------------------------------------------------------------ */
extern "C" void kernel_launch(void* const* d_in, const int* in_sizes, int n_in,
                              void* d_out, int out_size)
{
    (void)in_sizes; (void)n_in; (void)out_size;
    const float* x  = (const float*)d_in[0];
    const float* Wq = (const float*)d_in[1];
    const float* Wk = (const float*)d_in[2];
    const float* Wv = (const float*)d_in[3];
    const float* Wo = (const float*)d_in[4];
    const float* bo = (const float*)d_in[5];
    float* out = (float*)d_out;

    /* dynamic smem for attention exceeds the 48KB static default */
    cudaFuncSetAttribute(attn_kernel,
                         cudaFuncAttributeMaxDynamicSharedMemorySize,
                         ATTN_SMEM_BYTES);

    dim3 gq(DD / 128, NROWS / 128, 3);
    qkv_kernel<<<gq, 256>>>(x, Wq, Wk, Wv);

    dim3 ga(SS / 64, BB * HH);
    attn_kernel<<<ga, 256, ATTN_SMEM_BYTES>>>();

    dim3 go(DD / 128, NROWS / 128);
    out_kernel<<<go, 256>>>(Wo, bo, out);
}

// round 3
// speedup vs baseline: 1.5476x; 1.5476x over previous
#include <cuda_runtime.h>
#include <math.h>
#include <stdint.h>

#define BB 2
#define SS 2048
#define DD 1024
#define HH 16
#define DHD 64
#define NROWS (BB*SS)          /* 4096 */
#define ATTN_SCALE 0.125f      /* 1/sqrt(64) */
#define ROPE_LOG2C 0.4152410118609203f   /* log2(10000)/32 */

/* Scratch (allocation-free rule) */
__device__ float g_q[BB*HH*SS*DHD];
__device__ float g_k[BB*HH*SS*DHD];
__device__ float g_v[BB*HH*SS*DHD];
__device__ float g_ctx[(size_t)NROWS*DD];

__device__ __forceinline__ uint32_t tf32_of(float x) {
    uint32_t u;
    asm("cvt.rna.tf32.f32 %0, %1;" : "=r"(u) : "f"(x));
    return u;
}

#define MMA_TF32(c, a, b) \
    asm volatile("mma.sync.aligned.m16n8k8.row.col.f32.tf32.tf32.f32 " \
        "{%0,%1,%2,%3}, {%4,%5,%6,%7}, {%8,%9}, {%0,%1,%2,%3};" \
        : "+f"((c)[0]), "+f"((c)[1]), "+f"((c)[2]), "+f"((c)[3]) \
        : "r"((a)[0]), "r"((a)[1]), "r"((a)[2]), "r"((a)[3]), \
          "r"((b)[0]), "r"((b)[1]))

/* ------------------------------------------------------------------ */
/* tf32 mma.sync GEMM mainloop.                                       */
/* CTA tile 128x128, BK=16, 8 warps (2m x 4n), warp tile 64x32.       */
/* As[m][16+4], Bs[k][128+4], double buffered, 1 sync/stage.          */
/* acc[i][j][c]: i = m-tile (4 of 16 rows), j = n-tile (4 of 8 cols). */
/* ------------------------------------------------------------------ */
__device__ __forceinline__ void gemm128_tf32(
    const float* __restrict__ A, const float* __restrict__ W,
    int row0, int col0,
    float (*As)[128][20], float (*Bs)[16][132],
    float acc[4][4][4])
{
    const int tid  = threadIdx.x;
    const int lane = tid & 31, warp = tid >> 5;
    const int wm = warp >> 2, wn = warp & 3;
    const int ar = lane >> 2, ac = lane & 3;

    /* LDG thread mapping */
    const int a_r = tid >> 2, a_q = tid & 3;    /* A: rows a_r, a_r+64; 4 cols x4 */
    const int b_r = tid >> 5, b_n = tid & 31;   /* B: rows b_r, b_r+8; col grp b_n */

    float4 ra0, ra1, rb0, rb1;

    /* prologue: stage 0 */
    ra0 = *reinterpret_cast<const float4*>(&A[(size_t)(row0 + a_r) * DD + a_q * 4]);
    ra1 = *reinterpret_cast<const float4*>(&A[(size_t)(row0 + a_r + 64) * DD + a_q * 4]);
    rb0 = *reinterpret_cast<const float4*>(&W[(size_t)b_r * DD + col0 + b_n * 4]);
    rb1 = *reinterpret_cast<const float4*>(&W[(size_t)(b_r + 8) * DD + col0 + b_n * 4]);

#define STS_STAGE(buf) do { \
    float4 ca0 = make_float4(__uint_as_float(tf32_of(ra0.x)), __uint_as_float(tf32_of(ra0.y)), \
                             __uint_as_float(tf32_of(ra0.z)), __uint_as_float(tf32_of(ra0.w))); \
    float4 ca1 = make_float4(__uint_as_float(tf32_of(ra1.x)), __uint_as_float(tf32_of(ra1.y)), \
                             __uint_as_float(tf32_of(ra1.z)), __uint_as_float(tf32_of(ra1.w))); \
    float4 cb0 = make_float4(__uint_as_float(tf32_of(rb0.x)), __uint_as_float(tf32_of(rb0.y)), \
                             __uint_as_float(tf32_of(rb0.z)), __uint_as_float(tf32_of(rb0.w))); \
    float4 cb1 = make_float4(__uint_as_float(tf32_of(rb1.x)), __uint_as_float(tf32_of(rb1.y)), \
                             __uint_as_float(tf32_of(rb1.z)), __uint_as_float(tf32_of(rb1.w))); \
    *reinterpret_cast<float4*>(&As[buf][a_r][a_q * 4])      = ca0; \
    *reinterpret_cast<float4*>(&As[buf][a_r + 64][a_q * 4]) = ca1; \
    *reinterpret_cast<float4*>(&Bs[buf][b_r][b_n * 4])      = cb0; \
    *reinterpret_cast<float4*>(&Bs[buf][b_r + 8][b_n * 4])  = cb1; \
} while (0)

    STS_STAGE(0);
    __syncthreads();

    for (int kt = 0; kt < 64; kt++) {
        const int buf = kt & 1;
        if (kt < 63) {
            const int k0 = (kt + 1) * 16;
            ra0 = *reinterpret_cast<const float4*>(&A[(size_t)(row0 + a_r) * DD + k0 + a_q * 4]);
            ra1 = *reinterpret_cast<const float4*>(&A[(size_t)(row0 + a_r + 64) * DD + k0 + a_q * 4]);
            rb0 = *reinterpret_cast<const float4*>(&W[(size_t)(k0 + b_r) * DD + col0 + b_n * 4]);
            rb1 = *reinterpret_cast<const float4*>(&W[(size_t)(k0 + b_r + 8) * DD + col0 + b_n * 4]);
        }

#pragma unroll
        for (int k8 = 0; k8 < 2; k8++) {
            uint32_t a[4][4], b[4][2];
#pragma unroll
            for (int i = 0; i < 4; i++) {
                const int m = wm * 64 + i * 16 + ar;
                a[i][0] = __float_as_uint(As[buf][m][k8 * 8 + ac]);
                a[i][1] = __float_as_uint(As[buf][m + 8][k8 * 8 + ac]);
                a[i][2] = __float_as_uint(As[buf][m][k8 * 8 + ac + 4]);
                a[i][3] = __float_as_uint(As[buf][m + 8][k8 * 8 + ac + 4]);
            }
#pragma unroll
            for (int j = 0; j < 4; j++) {
                const int n = wn * 32 + j * 8 + ar;
                b[j][0] = __float_as_uint(Bs[buf][k8 * 8 + ac][n]);
                b[j][1] = __float_as_uint(Bs[buf][k8 * 8 + ac + 4][n]);
            }
#pragma unroll
            for (int i = 0; i < 4; i++)
#pragma unroll
                for (int j = 0; j < 4; j++)
                    MMA_TF32(acc[i][j], a[i], b[j]);
        }

        if (kt < 63) STS_STAGE(buf ^ 1);
        __syncthreads();
    }
#undef STS_STAGE
}

/* ------------------------------------------------------------------ */
/* QKV projection: grid (8, 32, 3), block 256. RoPE fused epilogue.   */
/* ------------------------------------------------------------------ */
__global__ __launch_bounds__(256)
void qkv_tc_kernel(const float* __restrict__ X,
                   const float* __restrict__ Wq,
                   const float* __restrict__ Wk,
                   const float* __restrict__ Wv)
{
    __shared__ float As[2][128][20];
    __shared__ float Bs[2][16][132];

    const int which = blockIdx.z;
    const float* __restrict__ W = (which == 0) ? Wq : ((which == 1) ? Wk : Wv);
    float* __restrict__ dst = (which == 0) ? g_q : ((which == 1) ? g_k : g_v);
    const int row0 = blockIdx.y * 128, col0 = blockIdx.x * 128;

    float acc[4][4][4];
#pragma unroll
    for (int i = 0; i < 4; i++)
#pragma unroll
        for (int j = 0; j < 4; j++)
#pragma unroll
            for (int c = 0; c < 4; c++) acc[i][j][c] = 0.f;

    gemm128_tf32(X, W, row0, col0, As, Bs, acc);

    const int lane = threadIdx.x & 31, warp = threadIdx.x >> 5;
    const int wm = warp >> 2, wn = warp & 3;
    const int ar = lane >> 2, ac = lane & 3;

#pragma unroll
    for (int i = 0; i < 4; i++) {
        const int r1 = row0 + wm * 64 + i * 16 + ar;
        const int r2 = r1 + 8;
        const int b1 = r1 >> 11, s1 = r1 & (SS - 1);
        const int b2 = r2 >> 11, s2 = r2 & (SS - 1);
#pragma unroll
        for (int j = 0; j < 4; j++) {
            const int col = col0 + wn * 32 + j * 8 + 2 * ac;
            const int h = col >> 6, dh = col & 63;
            float* p1 = dst + ((size_t)(b1 * HH + h) * SS + s1) * DHD + dh;
            float* p2 = dst + ((size_t)(b2 * HH + h) * SS + s2) * DHD + dh;
            if (which < 2) {
                const float freq = exp2f(-(float)(dh >> 1) * ROPE_LOG2C);
                float sn, cs;
                sincosf((float)s1 * freq, &sn, &cs);
                float e = acc[i][j][0], o = acc[i][j][1];
                *reinterpret_cast<float2*>(p1) = make_float2(e * cs - o * sn, e * sn + o * cs);
                sincosf((float)s2 * freq, &sn, &cs);
                e = acc[i][j][2]; o = acc[i][j][3];
                *reinterpret_cast<float2*>(p2) = make_float2(e * cs - o * sn, e * sn + o * cs);
            } else {
                *reinterpret_cast<float2*>(p1) = make_float2(acc[i][j][0], acc[i][j][1]);
                *reinterpret_cast<float2*>(p2) = make_float2(acc[i][j][2], acc[i][j][3]);
            }
        }
    }
}

/* ------------------------------------------------------------------ */
/* Output projection: grid (8, 32), block 256                         */
/* ------------------------------------------------------------------ */
__global__ __launch_bounds__(256)
void out_tc_kernel(const float* __restrict__ Wo,
                   const float* __restrict__ bo,
                   float* __restrict__ out)
{
    __shared__ float As[2][128][20];
    __shared__ float Bs[2][16][132];

    const int row0 = blockIdx.y * 128, col0 = blockIdx.x * 128;

    float acc[4][4][4];
#pragma unroll
    for (int i = 0; i < 4; i++)
#pragma unroll
        for (int j = 0; j < 4; j++)
#pragma unroll
            for (int c = 0; c < 4; c++) acc[i][j][c] = 0.f;

    gemm128_tf32(g_ctx, Wo, row0, col0, As, Bs, acc);

    const int lane = threadIdx.x & 31, warp = threadIdx.x >> 5;
    const int wm = warp >> 2, wn = warp & 3;
    const int ar = lane >> 2, ac = lane & 3;

#pragma unroll
    for (int i = 0; i < 4; i++) {
        const int r1 = row0 + wm * 64 + i * 16 + ar;
#pragma unroll
        for (int j = 0; j < 4; j++) {
            const int col = col0 + wn * 32 + j * 8 + 2 * ac;
            const float bx = bo[col], by = bo[col + 1];
            *reinterpret_cast<float2*>(&out[(size_t)r1 * DD + col]) =
                make_float2(acc[i][j][0] + bx, acc[i][j][1] + by);
            *reinterpret_cast<float2*>(&out[(size_t)(r1 + 8) * DD + col]) =
                make_float2(acc[i][j][2] + bx, acc[i][j][3] + by);
        }
    }
}

/* ------------------------------------------------------------------ */
/* Flash attention, fp32, causal (unchanged)                           */
/* ------------------------------------------------------------------ */
#define ATTN_SMEM_FLOATS (3 * 64 * 68 + 64 * 64)
#define ATTN_SMEM_BYTES  (ATTN_SMEM_FLOATS * 4)

__global__ __launch_bounds__(256)
void attn_kernel()
{
    extern __shared__ __align__(16) float sm[];
    float (*Qs)[68] = reinterpret_cast<float(*)[68]>(sm);
    float (*Ks)[68] = reinterpret_cast<float(*)[68]>(sm + 64 * 68);
    float (*Vs)[68] = reinterpret_cast<float(*)[68]>(sm + 2 * 64 * 68);
    float (*Ps)[64] = reinterpret_cast<float(*)[64]>(sm + 3 * 64 * 68);

    const int bh = blockIdx.y;
    const int qt = gridDim.x - 1 - blockIdx.x;

    const float* __restrict__ Q = g_q + (size_t)bh * SS * DHD;
    const float* __restrict__ K = g_k + (size_t)bh * SS * DHD;
    const float* __restrict__ V = g_v + (size_t)bh * SS * DHD;

    const int tid = threadIdx.x;
    const int warp = tid >> 5, lane = tid & 31;

    for (int i4 = tid; i4 < 64 * 16; i4 += 256) {
        int r = i4 >> 4, q = i4 & 15;
        *reinterpret_cast<float4*>(&Qs[r][q * 4]) =
            *reinterpret_cast<const float4*>(&Q[(size_t)(qt * 64 + r) * DHD + q * 4]);
    }

    float m[8], l[8], o0[8], o1[8];
#pragma unroll
    for (int rr = 0; rr < 8; rr++) { m[rr] = -1e30f; l[rr] = 0.f; o0[rr] = 0.f; o1[rr] = 0.f; }

    for (int kt = 0; kt <= qt; kt++) {
        __syncthreads();
        for (int i4 = tid; i4 < 64 * 16; i4 += 256) {
            int r = i4 >> 4, q = i4 & 15;
            *reinterpret_cast<float4*>(&Ks[r][q * 4]) =
                *reinterpret_cast<const float4*>(&K[(size_t)(kt * 64 + r) * DHD + q * 4]);
            *reinterpret_cast<float4*>(&Vs[r][q * 4]) =
                *reinterpret_cast<const float4*>(&V[(size_t)(kt * 64 + r) * DHD + q * 4]);
        }
        __syncthreads();

        float s0[8], s1[8];
#pragma unroll
        for (int rr = 0; rr < 8; rr++) { s0[rr] = 0.f; s1[rr] = 0.f; }

#pragma unroll
        for (int d4 = 0; d4 < 16; d4++) {
            float4 k0 = *reinterpret_cast<const float4*>(&Ks[lane][d4 * 4]);
            float4 k1 = *reinterpret_cast<const float4*>(&Ks[lane + 32][d4 * 4]);
#pragma unroll
            for (int rr = 0; rr < 8; rr++) {
                float4 q4 = *reinterpret_cast<const float4*>(&Qs[warp * 8 + rr][d4 * 4]);
                s0[rr] = fmaf(q4.x, k0.x, fmaf(q4.y, k0.y, fmaf(q4.z, k0.z, fmaf(q4.w, k0.w, s0[rr]))));
                s1[rr] = fmaf(q4.x, k1.x, fmaf(q4.y, k1.y, fmaf(q4.z, k1.z, fmaf(q4.w, k1.w, s1[rr]))));
            }
        }

        const bool diag = (kt == qt);
#pragma unroll
        for (int rr = 0; rr < 8; rr++) {
            float v0 = s0[rr] * ATTN_SCALE;
            float v1 = s1[rr] * ATTN_SCALE;
            int qrow = warp * 8 + rr;
            if (diag) {
                if (lane > qrow)      v0 = -1e30f;
                if (lane + 32 > qrow) v1 = -1e30f;
            }
            float mx = fmaxf(v0, v1);
#pragma unroll
            for (int off = 16; off; off >>= 1)
                mx = fmaxf(mx, __shfl_xor_sync(0xffffffffu, mx, off));
            float mnew = fmaxf(m[rr], mx);
            float p0 = __expf(v0 - mnew);
            float p1 = __expf(v1 - mnew);
            float corr = __expf(m[rr] - mnew);
            float ps = p0 + p1;
#pragma unroll
            for (int off = 16; off; off >>= 1)
                ps += __shfl_xor_sync(0xffffffffu, ps, off);
            l[rr] = l[rr] * corr + ps;
            o0[rr] *= corr;
            o1[rr] *= corr;
            m[rr] = mnew;
            Ps[warp * 8 + rr][lane]      = p0;
            Ps[warp * 8 + rr][lane + 32] = p1;
        }
        __syncwarp();

#pragma unroll
        for (int c4 = 0; c4 < 16; c4++) {
            float va[4], vb[4];
#pragma unroll
            for (int u = 0; u < 4; u++) {
                va[u] = Vs[c4 * 4 + u][lane];
                vb[u] = Vs[c4 * 4 + u][lane + 32];
            }
#pragma unroll
            for (int rr = 0; rr < 8; rr++) {
                float4 p = *reinterpret_cast<const float4*>(&Ps[warp * 8 + rr][c4 * 4]);
                o0[rr] = fmaf(p.x, va[0], fmaf(p.y, va[1], fmaf(p.z, va[2], fmaf(p.w, va[3], o0[rr]))));
                o1[rr] = fmaf(p.x, vb[0], fmaf(p.y, vb[1], fmaf(p.z, vb[2], fmaf(p.w, vb[3], o1[rr]))));
            }
        }
    }

    const int b_ = bh >> 4, h = bh & 15;
#pragma unroll
    for (int rr = 0; rr < 8; rr++) {
        int srow = qt * 64 + warp * 8 + rr;
        float inv = 1.0f / l[rr];
        float* orow = g_ctx + ((size_t)(b_ * SS + srow)) * DD + h * DHD;
        orow[lane]      = o0[rr] * inv;
        orow[lane + 32] = o1[rr] * inv;
    }
}

/* ------------------------------------------------------------------ */
extern "C" void kernel_launch(void* const* d_in, const int* in_sizes, int n_in,
                              void* d_out, int out_size)
{
    (void)in_sizes; (void)n_in; (void)out_size;
    const float* x  = (const float*)d_in[0];
    const float* Wq = (const float*)d_in[1];
    const float* Wk = (const float*)d_in[2];
    const float* Wv = (const float*)d_in[3];
    const float* Wo = (const float*)d_in[4];
    const float* bo = (const float*)d_in[5];
    float* out = (float*)d_out;

    cudaFuncSetAttribute(attn_kernel, cudaFuncAttributeMaxDynamicSharedMemorySize, ATTN_SMEM_BYTES);

    dim3 gq(DD / 128, NROWS / 128, 3);
    qkv_tc_kernel<<<gq, 256>>>(x, Wq, Wk, Wv);

    dim3 ga(SS / 64, BB * HH);
    attn_kernel<<<ga, 256, ATTN_SMEM_BYTES>>>();

    dim3 go(DD / 128, NROWS / 128);
    out_tc_kernel<<<go, 256>>>(Wo, bo, out);
}

// round 4
// speedup vs baseline: 2.7348x; 1.7672x over previous
#include <cuda_runtime.h>
#include <math.h>
#include <stdint.h>

#define BB 2
#define SS 2048
#define DD 1024
#define HH 16
#define DHD 64
#define NROWS (BB*SS)          /* 4096 */
#define ATTN_SCALE 0.125f      /* 1/sqrt(64) */
#define ROPE_LOG2C 0.4152410118609203f   /* log2(10000)/32 */

/* Scratch (allocation-free rule) */
__device__ float g_q[BB*HH*SS*DHD];
__device__ float g_k[BB*HH*SS*DHD];
__device__ float g_v[BB*HH*SS*DHD];
__device__ float g_ctx[(size_t)NROWS*DD];

__device__ __forceinline__ uint32_t tf32_of(float x) {
    uint32_t u;
    asm("cvt.rna.tf32.f32 %0, %1;" : "=r"(u) : "f"(x));
    return u;
}
__device__ __forceinline__ float tf32f(float x) {
    return __uint_as_float(tf32_of(x));
}

#define MMA_TF32(c, a, b) \
    asm volatile("mma.sync.aligned.m16n8k8.row.col.f32.tf32.tf32.f32 " \
        "{%0,%1,%2,%3}, {%4,%5,%6,%7}, {%8,%9}, {%0,%1,%2,%3};" \
        : "+f"((c)[0]), "+f"((c)[1]), "+f"((c)[2]), "+f"((c)[3]) \
        : "r"((a)[0]), "r"((a)[1]), "r"((a)[2]), "r"((a)[3]), \
          "r"((b)[0]), "r"((b)[1]))

/* ================================================================== */
/* tf32 mma.sync GEMM mainloop (unchanged from R3).                   */
/* ================================================================== */
__device__ __forceinline__ void gemm128_tf32(
    const float* __restrict__ A, const float* __restrict__ W,
    int row0, int col0,
    float (*As)[128][20], float (*Bs)[16][132],
    float acc[4][4][4])
{
    const int tid  = threadIdx.x;
    const int lane = tid & 31, warp = tid >> 5;
    const int wm = warp >> 2, wn = warp & 3;
    const int ar = lane >> 2, ac = lane & 3;

    const int a_r = tid >> 2, a_q = tid & 3;
    const int b_r = tid >> 5, b_n = tid & 31;

    float4 ra0, ra1, rb0, rb1;

    ra0 = *reinterpret_cast<const float4*>(&A[(size_t)(row0 + a_r) * DD + a_q * 4]);
    ra1 = *reinterpret_cast<const float4*>(&A[(size_t)(row0 + a_r + 64) * DD + a_q * 4]);
    rb0 = *reinterpret_cast<const float4*>(&W[(size_t)b_r * DD + col0 + b_n * 4]);
    rb1 = *reinterpret_cast<const float4*>(&W[(size_t)(b_r + 8) * DD + col0 + b_n * 4]);

#define STS_STAGE(buf) do { \
    float4 ca0 = make_float4(tf32f(ra0.x), tf32f(ra0.y), tf32f(ra0.z), tf32f(ra0.w)); \
    float4 ca1 = make_float4(tf32f(ra1.x), tf32f(ra1.y), tf32f(ra1.z), tf32f(ra1.w)); \
    float4 cb0 = make_float4(tf32f(rb0.x), tf32f(rb0.y), tf32f(rb0.z), tf32f(rb0.w)); \
    float4 cb1 = make_float4(tf32f(rb1.x), tf32f(rb1.y), tf32f(rb1.z), tf32f(rb1.w)); \
    *reinterpret_cast<float4*>(&As[buf][a_r][a_q * 4])      = ca0; \
    *reinterpret_cast<float4*>(&As[buf][a_r + 64][a_q * 4]) = ca1; \
    *reinterpret_cast<float4*>(&Bs[buf][b_r][b_n * 4])      = cb0; \
    *reinterpret_cast<float4*>(&Bs[buf][b_r + 8][b_n * 4])  = cb1; \
} while (0)

    STS_STAGE(0);
    __syncthreads();

    for (int kt = 0; kt < 64; kt++) {
        const int buf = kt & 1;
        if (kt < 63) {
            const int k0 = (kt + 1) * 16;
            ra0 = *reinterpret_cast<const float4*>(&A[(size_t)(row0 + a_r) * DD + k0 + a_q * 4]);
            ra1 = *reinterpret_cast<const float4*>(&A[(size_t)(row0 + a_r + 64) * DD + k0 + a_q * 4]);
            rb0 = *reinterpret_cast<const float4*>(&W[(size_t)(k0 + b_r) * DD + col0 + b_n * 4]);
            rb1 = *reinterpret_cast<const float4*>(&W[(size_t)(k0 + b_r + 8) * DD + col0 + b_n * 4]);
        }

#pragma unroll
        for (int k8 = 0; k8 < 2; k8++) {
            uint32_t a[4][4], b[4][2];
#pragma unroll
            for (int i = 0; i < 4; i++) {
                const int m = wm * 64 + i * 16 + ar;
                a[i][0] = __float_as_uint(As[buf][m][k8 * 8 + ac]);
                a[i][1] = __float_as_uint(As[buf][m + 8][k8 * 8 + ac]);
                a[i][2] = __float_as_uint(As[buf][m][k8 * 8 + ac + 4]);
                a[i][3] = __float_as_uint(As[buf][m + 8][k8 * 8 + ac + 4]);
            }
#pragma unroll
            for (int j = 0; j < 4; j++) {
                const int n = wn * 32 + j * 8 + ar;
                b[j][0] = __float_as_uint(Bs[buf][k8 * 8 + ac][n]);
                b[j][1] = __float_as_uint(Bs[buf][k8 * 8 + ac + 4][n]);
            }
#pragma unroll
            for (int i = 0; i < 4; i++)
#pragma unroll
                for (int j = 0; j < 4; j++)
                    MMA_TF32(acc[i][j], a[i], b[j]);
        }

        if (kt < 63) STS_STAGE(buf ^ 1);
        __syncthreads();
    }
#undef STS_STAGE
}

/* ------------------------------------------------------------------ */
__global__ __launch_bounds__(256)
void qkv_tc_kernel(const float* __restrict__ X,
                   const float* __restrict__ Wq,
                   const float* __restrict__ Wk,
                   const float* __restrict__ Wv)
{
    __shared__ float As[2][128][20];
    __shared__ float Bs[2][16][132];

    const int which = blockIdx.z;
    const float* __restrict__ W = (which == 0) ? Wq : ((which == 1) ? Wk : Wv);
    float* __restrict__ dst = (which == 0) ? g_q : ((which == 1) ? g_k : g_v);
    const int row0 = blockIdx.y * 128, col0 = blockIdx.x * 128;

    float acc[4][4][4];
#pragma unroll
    for (int i = 0; i < 4; i++)
#pragma unroll
        for (int j = 0; j < 4; j++)
#pragma unroll
            for (int c = 0; c < 4; c++) acc[i][j][c] = 0.f;

    gemm128_tf32(X, W, row0, col0, As, Bs, acc);

    const int lane = threadIdx.x & 31, warp = threadIdx.x >> 5;
    const int wm = warp >> 2, wn = warp & 3;
    const int ar = lane >> 2, ac = lane & 3;

#pragma unroll
    for (int i = 0; i < 4; i++) {
        const int r1 = row0 + wm * 64 + i * 16 + ar;
        const int r2 = r1 + 8;
        const int b1 = r1 >> 11, s1 = r1 & (SS - 1);
        const int b2 = r2 >> 11, s2 = r2 & (SS - 1);
#pragma unroll
        for (int j = 0; j < 4; j++) {
            const int col = col0 + wn * 32 + j * 8 + 2 * ac;
            const int h = col >> 6, dh = col & 63;
            float* p1 = dst + ((size_t)(b1 * HH + h) * SS + s1) * DHD + dh;
            float* p2 = dst + ((size_t)(b2 * HH + h) * SS + s2) * DHD + dh;
            if (which < 2) {
                const float freq = exp2f(-(float)(dh >> 1) * ROPE_LOG2C);
                float sn, cs;
                sincosf((float)s1 * freq, &sn, &cs);
                float e = acc[i][j][0], o = acc[i][j][1];
                *reinterpret_cast<float2*>(p1) = make_float2(e * cs - o * sn, e * sn + o * cs);
                sincosf((float)s2 * freq, &sn, &cs);
                e = acc[i][j][2]; o = acc[i][j][3];
                *reinterpret_cast<float2*>(p2) = make_float2(e * cs - o * sn, e * sn + o * cs);
            } else {
                *reinterpret_cast<float2*>(p1) = make_float2(acc[i][j][0], acc[i][j][1]);
                *reinterpret_cast<float2*>(p2) = make_float2(acc[i][j][2], acc[i][j][3]);
            }
        }
    }
}

/* ------------------------------------------------------------------ */
__global__ __launch_bounds__(256)
void out_tc_kernel(const float* __restrict__ Wo,
                   const float* __restrict__ bo,
                   float* __restrict__ out)
{
    __shared__ float As[2][128][20];
    __shared__ float Bs[2][16][132];

    const int row0 = blockIdx.y * 128, col0 = blockIdx.x * 128;

    float acc[4][4][4];
#pragma unroll
    for (int i = 0; i < 4; i++)
#pragma unroll
        for (int j = 0; j < 4; j++)
#pragma unroll
            for (int c = 0; c < 4; c++) acc[i][j][c] = 0.f;

    gemm128_tf32(g_ctx, Wo, row0, col0, As, Bs, acc);

    const int lane = threadIdx.x & 31, warp = threadIdx.x >> 5;
    const int wm = warp >> 2, wn = warp & 3;
    const int ar = lane >> 2, ac = lane & 3;

#pragma unroll
    for (int i = 0; i < 4; i++) {
        const int r1 = row0 + wm * 64 + i * 16 + ar;
#pragma unroll
        for (int j = 0; j < 4; j++) {
            const int col = col0 + wn * 32 + j * 8 + 2 * ac;
            const float bx = bo[col], by = bo[col + 1];
            *reinterpret_cast<float2*>(&out[(size_t)r1 * DD + col]) =
                make_float2(acc[i][j][0] + bx, acc[i][j][1] + by);
            *reinterpret_cast<float2*>(&out[(size_t)(r1 + 8) * DD + col]) =
                make_float2(acc[i][j][2] + bx, acc[i][j][3] + by);
        }
    }
}

/* ================================================================== */
/* Flash attention on tf32 mma.sync. 64x64 tiles, 128 threads.        */
/* Warp w owns q-rows [w*16, w*16+16). Scale folded into Q (exact).   */
/* ================================================================== */
#define AT_PAD  68
#define AT_VPAD 72
#define QS_OFF 0
#define KS_OFF (64*AT_PAD)
#define PS_OFF (2*64*AT_PAD)
#define VS_OFF (3*64*AT_PAD)
#define ATTN2_SMEM_FLOATS (3*64*AT_PAD + 64*AT_VPAD)
#define ATTN2_SMEM_BYTES  (ATTN2_SMEM_FLOATS * 4)

__global__ __launch_bounds__(128)
void attn_tc_kernel()
{
    extern __shared__ __align__(16) float sm[];
    float (*Qs)[AT_PAD]  = reinterpret_cast<float(*)[AT_PAD]>(sm + QS_OFF);
    float (*Ks)[AT_PAD]  = reinterpret_cast<float(*)[AT_PAD]>(sm + KS_OFF);
    float (*Ps)[AT_PAD]  = reinterpret_cast<float(*)[AT_PAD]>(sm + PS_OFF);
    float (*Vs)[AT_VPAD] = reinterpret_cast<float(*)[AT_VPAD]>(sm + VS_OFF);

    const int bh = blockIdx.y;
    const int qt = gridDim.x - 1 - blockIdx.x;   /* heavy-first */

    const float* __restrict__ Q = g_q + (size_t)bh * SS * DHD;
    const float* __restrict__ K = g_k + (size_t)bh * SS * DHD;
    const float* __restrict__ V = g_v + (size_t)bh * SS * DHD;

    const int tid  = threadIdx.x;
    const int warp = tid >> 5, lane = tid & 31;
    const int ar = lane >> 2, ac = lane & 3;
    const int mrow = warp * 16;

    /* load Q tile, scale by 1/8 (exact), tf32-round */
#pragma unroll
    for (int it = 0; it < 8; it++) {
        int i = tid + it * 128;
        int r = i >> 4, q4 = i & 15;
        float4 v = *reinterpret_cast<const float4*>(&Q[(size_t)(qt * 64 + r) * DHD + q4 * 4]);
        v.x = tf32f(v.x * ATTN_SCALE); v.y = tf32f(v.y * ATTN_SCALE);
        v.z = tf32f(v.z * ATTN_SCALE); v.w = tf32f(v.w * ATTN_SCALE);
        *reinterpret_cast<float4*>(&Qs[r][q4 * 4]) = v;
    }

    float m0 = -1e30f, m1 = -1e30f, l0 = 0.f, l1 = 0.f;
    float o[8][4];
#pragma unroll
    for (int j = 0; j < 8; j++)
#pragma unroll
        for (int c = 0; c < 4; c++) o[j][c] = 0.f;

    for (int kt = 0; kt <= qt; kt++) {
        __syncthreads();   /* prev K/V/P consumed */
#pragma unroll
        for (int it = 0; it < 8; it++) {
            int i = tid + it * 128;
            int r = i >> 4, q4 = i & 15;
            float4 kv = *reinterpret_cast<const float4*>(&K[(size_t)(kt * 64 + r) * DHD + q4 * 4]);
            kv.x = tf32f(kv.x); kv.y = tf32f(kv.y); kv.z = tf32f(kv.z); kv.w = tf32f(kv.w);
            *reinterpret_cast<float4*>(&Ks[r][q4 * 4]) = kv;
            float4 vv = *reinterpret_cast<const float4*>(&V[(size_t)(kt * 64 + r) * DHD + q4 * 4]);
            vv.x = tf32f(vv.x); vv.y = tf32f(vv.y); vv.z = tf32f(vv.z); vv.w = tf32f(vv.w);
            *reinterpret_cast<float4*>(&Vs[r][q4 * 4]) = vv;
        }
        __syncthreads();

        /* ---- S = Q Kᵀ ---- */
        float s[8][4];
#pragma unroll
        for (int j = 0; j < 8; j++)
#pragma unroll
            for (int c = 0; c < 4; c++) s[j][c] = 0.f;

#pragma unroll
        for (int k8 = 0; k8 < 8; k8++) {
            uint32_t a[4];
            a[0] = __float_as_uint(Qs[mrow + ar][k8 * 8 + ac]);
            a[1] = __float_as_uint(Qs[mrow + ar + 8][k8 * 8 + ac]);
            a[2] = __float_as_uint(Qs[mrow + ar][k8 * 8 + ac + 4]);
            a[3] = __float_as_uint(Qs[mrow + ar + 8][k8 * 8 + ac + 4]);
#pragma unroll
            for (int j = 0; j < 8; j++) {
                uint32_t b[2];
                b[0] = __float_as_uint(Ks[j * 8 + ar][k8 * 8 + ac]);
                b[1] = __float_as_uint(Ks[j * 8 + ar][k8 * 8 + ac + 4]);
                MMA_TF32(s[j], a, b);
            }
        }

        /* ---- causal mask on diagonal tile ---- */
        if (kt == qt) {
            const int r0 = mrow + ar, r1 = r0 + 8;
#pragma unroll
            for (int j = 0; j < 8; j++) {
                const int c0 = j * 8 + 2 * ac;
                if (c0 > r0)     s[j][0] = -1e30f;
                if (c0 + 1 > r0) s[j][1] = -1e30f;
                if (c0 > r1)     s[j][2] = -1e30f;
                if (c0 + 1 > r1) s[j][3] = -1e30f;
            }
        }

        /* ---- online softmax (rows r0 = mrow+ar, r1 = +8) ---- */
        float mx0 = -1e30f, mx1 = -1e30f;
#pragma unroll
        for (int j = 0; j < 8; j++) {
            mx0 = fmaxf(mx0, fmaxf(s[j][0], s[j][1]));
            mx1 = fmaxf(mx1, fmaxf(s[j][2], s[j][3]));
        }
        mx0 = fmaxf(mx0, __shfl_xor_sync(0xffffffffu, mx0, 1));
        mx0 = fmaxf(mx0, __shfl_xor_sync(0xffffffffu, mx0, 2));
        mx1 = fmaxf(mx1, __shfl_xor_sync(0xffffffffu, mx1, 1));
        mx1 = fmaxf(mx1, __shfl_xor_sync(0xffffffffu, mx1, 2));

        const float mn0 = fmaxf(m0, mx0), mn1 = fmaxf(m1, mx1);
        const float corr0 = __expf(m0 - mn0), corr1 = __expf(m1 - mn1);
        m0 = mn0; m1 = mn1;

        float ps0 = 0.f, ps1 = 0.f;
#pragma unroll
        for (int j = 0; j < 8; j++) {
            s[j][0] = __expf(s[j][0] - mn0);
            s[j][1] = __expf(s[j][1] - mn0);
            s[j][2] = __expf(s[j][2] - mn1);
            s[j][3] = __expf(s[j][3] - mn1);
            ps0 += s[j][0] + s[j][1];
            ps1 += s[j][2] + s[j][3];
        }
        ps0 += __shfl_xor_sync(0xffffffffu, ps0, 1);
        ps0 += __shfl_xor_sync(0xffffffffu, ps0, 2);
        ps1 += __shfl_xor_sync(0xffffffffu, ps1, 1);
        ps1 += __shfl_xor_sync(0xffffffffu, ps1, 2);

        l0 = l0 * corr0 + ps0;
        l1 = l1 * corr1 + ps1;
#pragma unroll
        for (int j = 0; j < 8; j++) {
            o[j][0] *= corr0; o[j][1] *= corr0;
            o[j][2] *= corr1; o[j][3] *= corr1;
        }

        /* ---- store P (tf32) to per-warp smem region ---- */
#pragma unroll
        for (int j = 0; j < 8; j++) {
            const int c0 = j * 8 + 2 * ac;
            *reinterpret_cast<float2*>(&Ps[mrow + ar][c0]) =
                make_float2(tf32f(s[j][0]), tf32f(s[j][1]));
            *reinterpret_cast<float2*>(&Ps[mrow + ar + 8][c0]) =
                make_float2(tf32f(s[j][2]), tf32f(s[j][3]));
        }
        __syncwarp();

        /* ---- O += P V ---- */
#pragma unroll
        for (int k8 = 0; k8 < 8; k8++) {
            uint32_t a[4];
            a[0] = __float_as_uint(Ps[mrow + ar][k8 * 8 + ac]);
            a[1] = __float_as_uint(Ps[mrow + ar + 8][k8 * 8 + ac]);
            a[2] = __float_as_uint(Ps[mrow + ar][k8 * 8 + ac + 4]);
            a[3] = __float_as_uint(Ps[mrow + ar + 8][k8 * 8 + ac + 4]);
#pragma unroll
            for (int j = 0; j < 8; j++) {
                uint32_t b[2];
                b[0] = __float_as_uint(Vs[k8 * 8 + ac][j * 8 + ar]);
                b[1] = __float_as_uint(Vs[k8 * 8 + ac + 4][j * 8 + ar]);
                MMA_TF32(o[j], a, b);
            }
        }
    }

    /* epilogue: normalize, write ctx [B*S, D] */
    const int b_ = bh >> 4, h = bh & 15;
    const float inv0 = 1.0f / l0, inv1 = 1.0f / l1;
    const int s0 = qt * 64 + mrow + ar, s1 = s0 + 8;
#pragma unroll
    for (int j = 0; j < 8; j++) {
        const int col = h * DHD + j * 8 + 2 * ac;
        *reinterpret_cast<float2*>(&g_ctx[(size_t)(b_ * SS + s0) * DD + col]) =
            make_float2(o[j][0] * inv0, o[j][1] * inv0);
        *reinterpret_cast<float2*>(&g_ctx[(size_t)(b_ * SS + s1) * DD + col]) =
            make_float2(o[j][2] * inv1, o[j][3] * inv1);
    }
}

/* ------------------------------------------------------------------ */
extern "C" void kernel_launch(void* const* d_in, const int* in_sizes, int n_in,
                              void* d_out, int out_size)
{
    (void)in_sizes; (void)n_in; (void)out_size;
    const float* x  = (const float*)d_in[0];
    const float* Wq = (const float*)d_in[1];
    const float* Wk = (const float*)d_in[2];
    const float* Wv = (const float*)d_in[3];
    const float* Wo = (const float*)d_in[4];
    const float* bo = (const float*)d_in[5];
    float* out = (float*)d_out;

    cudaFuncSetAttribute(attn_tc_kernel,
                         cudaFuncAttributeMaxDynamicSharedMemorySize,
                         ATTN2_SMEM_BYTES);

    dim3 gq(DD / 128, NROWS / 128, 3);
    qkv_tc_kernel<<<gq, 256>>>(x, Wq, Wk, Wv);

    dim3 ga(SS / 64, BB * HH);
    attn_tc_kernel<<<ga, 128, ATTN2_SMEM_BYTES>>>();

    dim3 go(DD / 128, NROWS / 128);
    out_tc_kernel<<<go, 256>>>(Wo, bo, out);
}

// round 5
// speedup vs baseline: 3.0609x; 1.1192x over previous
#include <cuda_runtime.h>
#include <math.h>
#include <stdint.h>

#define BB 2
#define SS 2048
#define DD 1024
#define HH 16
#define DHD 64
#define NROWS (BB*SS)          /* 4096 */
#define ROPE_LOG2C 0.4152410118609203f   /* log2(10000)/32 */

/* Scratch (allocation-free rule) */
__device__ float g_x[(size_t)NROWS*DD];
__device__ float g_wq[DD*DD];
__device__ float g_wk[DD*DD];
__device__ float g_wv[DD*DD];
__device__ float g_wo[DD*DD];
__device__ float g_q[BB*HH*SS*DHD];
__device__ float g_k[BB*HH*SS*DHD];
__device__ float g_v[BB*HH*SS*DHD];
__device__ float g_ctx[(size_t)NROWS*DD];

__device__ __forceinline__ uint32_t tf32_of(float x) {
    uint32_t u;
    asm("cvt.rna.tf32.f32 %0, %1;" : "=r"(u) : "f"(x));
    return u;
}
__device__ __forceinline__ float tf32f(float x) {
    return __uint_as_float(tf32_of(x));
}
__device__ __forceinline__ uint32_t smem_u32_of(const void* p) {
    uint32_t a;
    asm("{ .reg .u64 t; cvta.to.shared.u64 t, %1; cvt.u32.u64 %0, t; }" : "=r"(a) : "l"(p));
    return a;
}

#define MMA_TF32(c, a, b) \
    asm volatile("mma.sync.aligned.m16n8k8.row.col.f32.tf32.tf32.f32 " \
        "{%0,%1,%2,%3}, {%4,%5,%6,%7}, {%8,%9}, {%0,%1,%2,%3};" \
        : "+f"((c)[0]), "+f"((c)[1]), "+f"((c)[2]), "+f"((c)[3]) \
        : "r"((a)[0]), "r"((a)[1]), "r"((a)[2]), "r"((a)[3]), \
          "r"((b)[0]), "r"((b)[1]))

#define CP16(dst, src) \
    asm volatile("cp.async.cg.shared.global [%0], [%1], 16;" :: "r"(dst), "l"(src))
#define CPCOMMIT() asm volatile("cp.async.commit_group;" ::: "memory")
#define CPWAIT(n)  asm volatile("cp.async.wait_group %0;" :: "n"(n) : "memory")

/* ================================================================== */
/* Pre-round pass: tf32-rna all GEMM inputs once.                     */
/* grid (1024, 8) x 256: seg 0-3 = quarters of X, 4-7 = Wq/Wk/Wv/Wo.  */
/* ================================================================== */
__global__ void round_kernel(const float* __restrict__ X,
                             const float* __restrict__ Wq,
                             const float* __restrict__ Wk,
                             const float* __restrict__ Wv,
                             const float* __restrict__ Wo)
{
    const int seg = blockIdx.y;
    const size_t idx = (size_t)(blockIdx.x * 256 + threadIdx.x) * 4;
    const float* src;
    float* dst;
    size_t off = 0;
    if (seg < 4) { src = X; dst = g_x; off = (size_t)seg * ((size_t)NROWS / 4) * DD; }
    else if (seg == 4) { src = Wq; dst = g_wq; }
    else if (seg == 5) { src = Wk; dst = g_wk; }
    else if (seg == 6) { src = Wv; dst = g_wv; }
    else               { src = Wo; dst = g_wo; }
    float4 v = *reinterpret_cast<const float4*>(src + off + idx);
    v.x = tf32f(v.x); v.y = tf32f(v.y); v.z = tf32f(v.z); v.w = tf32f(v.w);
    *reinterpret_cast<float4*>(dst + off + idx) = v;
}

/* ================================================================== */
/* GEMM: CTA 128x128, 4 warps (warp tile 64x64), BK=16, cp.async x4.  */
/* ================================================================== */
#define GM_APAD 20
#define GM_BPAD 132
#define GM_ABYTES (128*GM_APAD*4)          /* 10240 */
#define GM_BBYTES (16*GM_BPAD*4)           /* 8448  */
#define GM_STAGE  (GM_ABYTES + GM_BBYTES)  /* 18688 */
#define GM_NSTAGE 4
#define GM_SMEM   (GM_NSTAGE * GM_STAGE)   /* 74752 */

__device__ __forceinline__ void gemm_issue_stage(
    const float* __restrict__ A, const float* __restrict__ W,
    int row0, int col0, int s, uint32_t sm)
{
    const int tid = threadIdx.x;
    const uint32_t base = sm + (uint32_t)(s & 3) * GM_STAGE;
    const int am = tid >> 2, aq = tid & 3;
    const int bk = tid >> 5, bn = tid & 31;
#pragma unroll
    for (int it = 0; it < 4; it++) {
        int r = am + it * 32;
        CP16(base + (uint32_t)(r * (GM_APAD*4) + aq * 16),
             A + (size_t)(row0 + r) * DD + s * 16 + aq * 4);
    }
    const uint32_t bbase = base + GM_ABYTES;
#pragma unroll
    for (int it = 0; it < 4; it++) {
        int r = bk + it * 4;
        CP16(bbase + (uint32_t)(r * (GM_BPAD*4) + bn * 16),
             W + (size_t)(s * 16 + r) * DD + col0 + bn * 4);
    }
}

__device__ __forceinline__ void gemm_tc2(
    const float* __restrict__ A, const float* __restrict__ W,
    int row0, int col0, float* smem, float acc[4][8][4])
{
    const uint32_t sm = smem_u32_of(smem);
    const int lane = threadIdx.x & 31, warp = threadIdx.x >> 5;
    const int wm = warp >> 1, wn = warp & 1;
    const int ar = lane >> 2, ac = lane & 3;

    gemm_issue_stage(A, W, row0, col0, 0, sm); CPCOMMIT();
    gemm_issue_stage(A, W, row0, col0, 1, sm); CPCOMMIT();
    gemm_issue_stage(A, W, row0, col0, 2, sm); CPCOMMIT();

    for (int kt = 0; kt < 64; kt++) {
        CPWAIT(2);
        __syncthreads();
        if (kt + 3 < 64) gemm_issue_stage(A, W, row0, col0, kt + 3, sm);
        CPCOMMIT();

        const float* As = smem + (size_t)(kt & 3) * (GM_STAGE / 4);
        const float* Bs = As + GM_ABYTES / 4;
#pragma unroll
        for (int k8 = 0; k8 < 2; k8++) {
            uint32_t a[4][4], b[8][2];
#pragma unroll
            for (int i = 0; i < 4; i++) {
                const int m = wm * 64 + i * 16 + ar;
                a[i][0] = __float_as_uint(As[m * GM_APAD + k8 * 8 + ac]);
                a[i][1] = __float_as_uint(As[(m + 8) * GM_APAD + k8 * 8 + ac]);
                a[i][2] = __float_as_uint(As[m * GM_APAD + k8 * 8 + ac + 4]);
                a[i][3] = __float_as_uint(As[(m + 8) * GM_APAD + k8 * 8 + ac + 4]);
            }
#pragma unroll
            for (int j = 0; j < 8; j++) {
                const int n = wn * 64 + j * 8 + ar;
                b[j][0] = __float_as_uint(Bs[(k8 * 8 + ac) * GM_BPAD + n]);
                b[j][1] = __float_as_uint(Bs[(k8 * 8 + ac + 4) * GM_BPAD + n]);
            }
#pragma unroll
            for (int i = 0; i < 4; i++)
#pragma unroll
                for (int j = 0; j < 8; j++)
                    MMA_TF32(acc[i][j], a[i], b[j]);
        }
    }
}

/* ------------------------------------------------------------------ */
__global__ void __launch_bounds__(128, 2)
qkv_tc2_kernel()
{
    extern __shared__ __align__(16) float smem[];
    const int which = blockIdx.z;
    const float* __restrict__ W = (which == 0) ? g_wq : ((which == 1) ? g_wk : g_wv);
    float* __restrict__ dst = (which == 0) ? g_q : ((which == 1) ? g_k : g_v);
    const int row0 = blockIdx.y * 128, col0 = blockIdx.x * 128;

    float acc[4][8][4];
#pragma unroll
    for (int i = 0; i < 4; i++)
#pragma unroll
        for (int j = 0; j < 8; j++)
#pragma unroll
            for (int c = 0; c < 4; c++) acc[i][j][c] = 0.f;

    gemm_tc2(g_x, W, row0, col0, smem, acc);

    const int lane = threadIdx.x & 31, warp = threadIdx.x >> 5;
    const int wm = warp >> 1, wn = warp & 1;
    const int ar = lane >> 2, ac = lane & 3;
    const int h = (col0 >> 6) + wn;     /* warp n-tile 64 == one head */
    const bool rope = (which < 2);

    float freqs[8];
#pragma unroll
    for (int j = 0; j < 8; j++)
        freqs[j] = exp2f(-(float)(j * 4 + ac) * ROPE_LOG2C);

#pragma unroll
    for (int i = 0; i < 4; i++) {
#pragma unroll
        for (int half = 0; half < 2; half++) {
            const int row = row0 + wm * 64 + i * 16 + ar + half * 8;
            const int b_ = row >> 11, s = row & (SS - 1);
            float* drow = dst + ((size_t)(b_ * HH + h) * SS + s) * DHD;
            const float sf = (float)s;
#pragma unroll
            for (int j = 0; j < 8; j++) {
                const int dh = j * 8 + 2 * ac;
                const float e = acc[i][j][half * 2], o = acc[i][j][half * 2 + 1];
                float2 w2;
                if (rope) {
                    float sn, cs;
                    sincosf(sf * freqs[j], &sn, &cs);
                    w2 = make_float2(tf32f(e * cs - o * sn), tf32f(e * sn + o * cs));
                } else {
                    w2 = make_float2(tf32f(e), tf32f(o));
                }
                *reinterpret_cast<float2*>(&drow[dh]) = w2;
            }
        }
    }
}

/* ------------------------------------------------------------------ */
__global__ void __launch_bounds__(128, 2)
out_tc2_kernel(const float* __restrict__ bo, float* __restrict__ out)
{
    extern __shared__ __align__(16) float smem[];
    const int row0 = blockIdx.y * 128, col0 = blockIdx.x * 128;

    float acc[4][8][4];
#pragma unroll
    for (int i = 0; i < 4; i++)
#pragma unroll
        for (int j = 0; j < 8; j++)
#pragma unroll
            for (int c = 0; c < 4; c++) acc[i][j][c] = 0.f;

    gemm_tc2(g_ctx, g_wo, row0, col0, smem, acc);

    const int lane = threadIdx.x & 31, warp = threadIdx.x >> 5;
    const int wm = warp >> 1, wn = warp & 1;
    const int ar = lane >> 2, ac = lane & 3;

#pragma unroll
    for (int i = 0; i < 4; i++) {
        const int r = row0 + wm * 64 + i * 16 + ar;
#pragma unroll
        for (int j = 0; j < 8; j++) {
            const int col = col0 + wn * 64 + j * 8 + 2 * ac;
            const float bx = bo[col], by = bo[col + 1];
            *reinterpret_cast<float2*>(&out[(size_t)r * DD + col]) =
                make_float2(acc[i][j][0] + bx, acc[i][j][1] + by);
            *reinterpret_cast<float2*>(&out[(size_t)(r + 8) * DD + col]) =
                make_float2(acc[i][j][2] + bx, acc[i][j][3] + by);
        }
    }
}

/* ================================================================== */
/* Flash attention v2: q-tile 128, k-tile 64, 4 warps x 32 q-rows.    */
/* Q frags in registers; Q smem region reused for P. cp.async K/V x2.*/
/* ================================================================== */
#define AT_QPAD 68
#define AT_KPAD 68
#define AT_VPAD 72
#define AT_QP_BYTES (128*AT_QPAD*4)   /* 34816 */
#define AT_K_BYTES  (64*AT_KPAD*4)    /* 17408 */
#define AT_V_BYTES  (64*AT_VPAD*4)    /* 18432 */
#define AT_KOFF     AT_QP_BYTES
#define AT_VOFF     (AT_QP_BYTES + 2*AT_K_BYTES)
#define AT_SMEM     (AT_QP_BYTES + 2*AT_K_BYTES + 2*AT_V_BYTES)  /* 106496 */

__global__ void __launch_bounds__(128, 2)
attn_tc2_kernel()
{
    extern __shared__ __align__(16) float smem[];
    const uint32_t sm = smem_u32_of(smem);
    const int bh = blockIdx.y;
    const int qt = gridDim.x - 1 - blockIdx.x;   /* heavy-first */
    const float* __restrict__ Q = g_q + (size_t)bh * SS * DHD;
    const float* __restrict__ K = g_k + (size_t)bh * SS * DHD;
    const float* __restrict__ V = g_v + (size_t)bh * SS * DHD;

    const int tid = threadIdx.x;
    const int lane = tid & 31, warp = tid >> 5;
    const int ar = lane >> 2, ac = lane & 3;
    const int nk = 2 * qt + 2;

    auto issue_kv = [&](int kt, int buf) {
#pragma unroll
        for (int it = 0; it < 8; it++) {
            const int idx = tid + it * 128;
            const int r = idx >> 4, q = idx & 15;
            CP16(sm + (uint32_t)(AT_KOFF + buf * AT_K_BYTES + r * (AT_KPAD*4) + q * 16),
                 K + (size_t)(kt * 64 + r) * DHD + q * 4);
            CP16(sm + (uint32_t)(AT_VOFF + buf * AT_V_BYTES + r * (AT_VPAD*4) + q * 16),
                 V + (size_t)(kt * 64 + r) * DHD + q * 4);
        }
    };

    /* G0: Q + K0/V0; G1: K1/V1 */
#pragma unroll
    for (int it = 0; it < 16; it++) {
        const int idx = tid + it * 128;
        const int r = idx >> 4, q = idx & 15;
        CP16(sm + (uint32_t)(r * (AT_QPAD*4) + q * 16),
             Q + (size_t)(qt * 128 + r) * DHD + q * 4);
    }
    issue_kv(0, 0);
    CPCOMMIT();
    issue_kv(1, 1);
    CPCOMMIT();

    CPWAIT(1);
    __syncthreads();

    /* Q fragments -> registers (warp-private rows) */
    uint32_t qf[2][8][4];
    {
        const float* Qs = smem;
#pragma unroll
        for (int i = 0; i < 2; i++) {
            const int r = warp * 32 + i * 16 + ar;
#pragma unroll
            for (int k8 = 0; k8 < 8; k8++) {
                qf[i][k8][0] = __float_as_uint(Qs[r * AT_QPAD + k8 * 8 + ac]);
                qf[i][k8][1] = __float_as_uint(Qs[(r + 8) * AT_QPAD + k8 * 8 + ac]);
                qf[i][k8][2] = __float_as_uint(Qs[r * AT_QPAD + k8 * 8 + ac + 4]);
                qf[i][k8][3] = __float_as_uint(Qs[(r + 8) * AT_QPAD + k8 * 8 + ac + 4]);
            }
        }
    }

    float m[2][2], l[2][2], o[2][8][4];
#pragma unroll
    for (int i = 0; i < 2; i++) {
        m[i][0] = m[i][1] = -1e30f;
        l[i][0] = l[i][1] = 0.f;
#pragma unroll
        for (int j = 0; j < 8; j++)
#pragma unroll
            for (int c = 0; c < 4; c++) o[i][j][c] = 0.f;
    }

    float* Ps = smem;   /* reuse Q region for P (warp-private rows) */

    for (int kt = 0; kt < nk; kt++) {
        CPWAIT(1);
        __syncthreads();
        const int buf = kt & 1;
        const float* Ks = smem + (AT_KOFF + buf * AT_K_BYTES) / 4;
        const float* Vs = smem + (AT_VOFF + buf * AT_V_BYTES) / 4;

        /* ---- S = Q K^T ---- */
        float s[2][8][4];
#pragma unroll
        for (int i = 0; i < 2; i++)
#pragma unroll
            for (int j = 0; j < 8; j++)
#pragma unroll
                for (int c = 0; c < 4; c++) s[i][j][c] = 0.f;

#pragma unroll
        for (int k8 = 0; k8 < 8; k8++) {
#pragma unroll
            for (int j = 0; j < 8; j++) {
                uint32_t kb[2];
                kb[0] = __float_as_uint(Ks[(j * 8 + ar) * AT_KPAD + k8 * 8 + ac]);
                kb[1] = __float_as_uint(Ks[(j * 8 + ar) * AT_KPAD + k8 * 8 + ac + 4]);
                MMA_TF32(s[0][j], qf[0][k8], kb);
                MMA_TF32(s[1][j], qf[1][k8], kb);
            }
        }

        /* ---- scale + causal mask ---- */
        const bool domask = (kt >= 2 * qt);
        const int dshift = (kt - 2 * qt) * 64;
#pragma unroll
        for (int i = 0; i < 2; i++) {
            const int r0 = warp * 32 + i * 16 + ar, r1 = r0 + 8;
#pragma unroll
            for (int j = 0; j < 8; j++) {
                float v0 = s[i][j][0] * 0.125f, v1 = s[i][j][1] * 0.125f;
                float v2 = s[i][j][2] * 0.125f, v3 = s[i][j][3] * 0.125f;
                if (domask) {
                    const int c = j * 8 + 2 * ac + dshift;
                    if (c     > r0) v0 = -1e30f;
                    if (c + 1 > r0) v1 = -1e30f;
                    if (c     > r1) v2 = -1e30f;
                    if (c + 1 > r1) v3 = -1e30f;
                }
                s[i][j][0] = v0; s[i][j][1] = v1; s[i][j][2] = v2; s[i][j][3] = v3;
            }
        }

        /* ---- online softmax per row-slot ---- */
#pragma unroll
        for (int i = 0; i < 2; i++) {
            float mx0 = -1e30f, mx1 = -1e30f;
#pragma unroll
            for (int j = 0; j < 8; j++) {
                mx0 = fmaxf(mx0, fmaxf(s[i][j][0], s[i][j][1]));
                mx1 = fmaxf(mx1, fmaxf(s[i][j][2], s[i][j][3]));
            }
            mx0 = fmaxf(mx0, __shfl_xor_sync(0xffffffffu, mx0, 1));
            mx0 = fmaxf(mx0, __shfl_xor_sync(0xffffffffu, mx0, 2));
            mx1 = fmaxf(mx1, __shfl_xor_sync(0xffffffffu, mx1, 1));
            mx1 = fmaxf(mx1, __shfl_xor_sync(0xffffffffu, mx1, 2));

            const float mn0 = fmaxf(m[i][0], mx0), mn1 = fmaxf(m[i][1], mx1);
            const float corr0 = __expf(m[i][0] - mn0), corr1 = __expf(m[i][1] - mn1);
            m[i][0] = mn0; m[i][1] = mn1;

            const int r0 = warp * 32 + i * 16 + ar;
            float ps0 = 0.f, ps1 = 0.f;
#pragma unroll
            for (int j = 0; j < 8; j++) {
                const float p0 = __expf(s[i][j][0] - mn0);
                const float p1 = __expf(s[i][j][1] - mn0);
                const float p2 = __expf(s[i][j][2] - mn1);
                const float p3 = __expf(s[i][j][3] - mn1);
                ps0 += p0 + p1; ps1 += p2 + p3;
                const int c = j * 8 + 2 * ac;
                *reinterpret_cast<float2*>(&Ps[r0 * AT_QPAD + c]) =
                    make_float2(tf32f(p0), tf32f(p1));
                *reinterpret_cast<float2*>(&Ps[(r0 + 8) * AT_QPAD + c]) =
                    make_float2(tf32f(p2), tf32f(p3));
            }
            ps0 += __shfl_xor_sync(0xffffffffu, ps0, 1);
            ps0 += __shfl_xor_sync(0xffffffffu, ps0, 2);
            ps1 += __shfl_xor_sync(0xffffffffu, ps1, 1);
            ps1 += __shfl_xor_sync(0xffffffffu, ps1, 2);
            l[i][0] = l[i][0] * corr0 + ps0;
            l[i][1] = l[i][1] * corr1 + ps1;
#pragma unroll
            for (int j = 0; j < 8; j++) {
                o[i][j][0] *= corr0; o[i][j][1] *= corr0;
                o[i][j][2] *= corr1; o[i][j][3] *= corr1;
            }
        }
        __syncwarp();

        /* ---- O += P V ---- */
#pragma unroll
        for (int k8 = 0; k8 < 8; k8++) {
            uint32_t pa[2][4];
#pragma unroll
            for (int i = 0; i < 2; i++) {
                const int r0 = warp * 32 + i * 16 + ar;
                pa[i][0] = __float_as_uint(Ps[r0 * AT_QPAD + k8 * 8 + ac]);
                pa[i][1] = __float_as_uint(Ps[(r0 + 8) * AT_QPAD + k8 * 8 + ac]);
                pa[i][2] = __float_as_uint(Ps[r0 * AT_QPAD + k8 * 8 + ac + 4]);
                pa[i][3] = __float_as_uint(Ps[(r0 + 8) * AT_QPAD + k8 * 8 + ac + 4]);
            }
#pragma unroll
            for (int j = 0; j < 8; j++) {
                uint32_t vb[2];
                vb[0] = __float_as_uint(Vs[(k8 * 8 + ac) * AT_VPAD + j * 8 + ar]);
                vb[1] = __float_as_uint(Vs[(k8 * 8 + ac + 4) * AT_VPAD + j * 8 + ar]);
                MMA_TF32(o[0][j], pa[0], vb);
                MMA_TF32(o[1][j], pa[1], vb);
            }
        }

        __syncthreads();
        if (kt + 2 < nk) issue_kv(kt + 2, buf);
        CPCOMMIT();
    }

    /* epilogue: normalize, write ctx [B*S, D] (tf32-rounded for out GEMM) */
    const int b_ = bh >> 4, h = bh & (HH - 1);
#pragma unroll
    for (int i = 0; i < 2; i++) {
        const float inv0 = 1.0f / l[i][0], inv1 = 1.0f / l[i][1];
        const int r0 = qt * 128 + warp * 32 + i * 16 + ar;
        float* p0 = g_ctx + (size_t)(b_ * SS + r0) * DD + h * DHD;
        float* p1 = g_ctx + (size_t)(b_ * SS + r0 + 8) * DD + h * DHD;
#pragma unroll
        for (int j = 0; j < 8; j++) {
            const int c = j * 8 + 2 * ac;
            *reinterpret_cast<float2*>(&p0[c]) =
                make_float2(tf32f(o[i][j][0] * inv0), tf32f(o[i][j][1] * inv0));
            *reinterpret_cast<float2*>(&p1[c]) =
                make_float2(tf32f(o[i][j][2] * inv1), tf32f(o[i][j][3] * inv1));
        }
    }
}

/* ------------------------------------------------------------------ */
extern "C" void kernel_launch(void* const* d_in, const int* in_sizes, int n_in,
                              void* d_out, int out_size)
{
    (void)in_sizes; (void)n_in; (void)out_size;
    const float* x  = (const float*)d_in[0];
    const float* Wq = (const float*)d_in[1];
    const float* Wk = (const float*)d_in[2];
    const float* Wv = (const float*)d_in[3];
    const float* Wo = (const float*)d_in[4];
    const float* bo = (const float*)d_in[5];
    float* out = (float*)d_out;

    cudaFuncSetAttribute(qkv_tc2_kernel,  cudaFuncAttributeMaxDynamicSharedMemorySize, GM_SMEM);
    cudaFuncSetAttribute(out_tc2_kernel,  cudaFuncAttributeMaxDynamicSharedMemorySize, GM_SMEM);
    cudaFuncSetAttribute(attn_tc2_kernel, cudaFuncAttributeMaxDynamicSharedMemorySize, AT_SMEM);

    round_kernel<<<dim3(1024, 8), 256>>>(x, Wq, Wk, Wv, Wo);

    dim3 gq(DD / 128, NROWS / 128, 3);
    qkv_tc2_kernel<<<gq, 128, GM_SMEM>>>();

    dim3 ga(SS / 128, BB * HH);
    attn_tc2_kernel<<<ga, 128, AT_SMEM>>>();

    dim3 go(DD / 128, NROWS / 128);
    out_tc2_kernel<<<go, 128, GM_SMEM>>>(bo, out);
}